// round 1
// baseline (speedup 1.0000x reference)
#include <cuda_runtime.h>

#define Bn 8
#define Ln 16384
#define Cn 128
#define Hn 4
#define Dn 32
#define OC3 384
#define BLn (Bn*Ln)

// ---- scratch (device globals; no allocation allowed) ----
__device__ float g_qkv[Bn*OC3*Ln];     // [b, 3C, L]  (q overwritten in-place by softmax)
__device__ float g_o[Bn*Cn*Ln];        // pre-norm output [b, C, L]
__device__ float g_ctx[Bn*Hn*Dn*Dn];   // context accumulators [bh, c, d]
__device__ float g_Z[Bn*Hn*Dn];        // sum exp(k) per [bh, c]
__device__ float g_A[Bn*Cn*Cn];        // folded W_out @ blockdiag(ctx_norm)
__device__ float g_bsum[Bn];
__device__ float g_bsq[Bn];

// ---- packed dual-fp32 helpers (Blackwell f32x2 path) ----
__device__ __forceinline__ unsigned long long pack2(float a, float b) {
    unsigned long long r;
    asm("mov.b64 %0,{%1,%2};" : "=l"(r) : "f"(a), "f"(b));
    return r;
}
__device__ __forceinline__ void unpack2(unsigned long long v, float& a, float& b) {
    asm("mov.b64 {%0,%1},%2;" : "=f"(a), "=f"(b) : "l"(v));
}
__device__ __forceinline__ unsigned long long ffma2(unsigned long long a,
                                                    unsigned long long b,
                                                    unsigned long long c) {
    unsigned long long r;
    asm("fma.rn.f32x2 %0,%1,%2,%3;" : "=l"(r) : "l"(a), "l"(b), "l"(c));
    return r;
}

// ---- K0: zero the accumulators (graph replays!) ----
__global__ void k_zero() {
    int i = blockIdx.x * 256 + threadIdx.x;
    if (i < Bn*Hn*Dn*Dn) g_ctx[i] = 0.f;
    if (i < Bn*Hn*Dn)    g_Z[i]   = 0.f;
    if (i < Bn)          { g_bsum[i] = 0.f; g_bsq[i] = 0.f; }
}

// ---- K1: qkv[b, o, l] = sum_c Wqkv[o,c] x[b,l,c] ----
// block: 128 out-channels x 128 positions, K=128. 256 threads, 8x8 micro (as 8x4 f32x2).
__global__ __launch_bounds__(256) void k_qkv(const float* __restrict__ x,
                                             const float* __restrict__ Wqkv) {
    __shared__ __align__(16) float Ws[16][132];
    __shared__ __align__(16) float Xs[16][132];
    int t  = threadIdx.x;
    int p0 = blockIdx.x * 128;   // global position
    int m0 = blockIdx.y * 128;   // out-channel tile (0,128,256)
    int tr = t >> 4, tc = t & 15;

    unsigned long long acc[8][4];
#pragma unroll
    for (int i = 0; i < 8; i++)
#pragma unroll
        for (int j = 0; j < 4; j++) acc[i][j] = 0ull;

    for (int k0 = 0; k0 < Cn; k0 += 16) {
#pragma unroll
        for (int it = 0; it < 8; it++) {
            int idx = it * 256 + t;
            int m = idx >> 4, kk = idx & 15;
            Ws[kk][m] = Wqkv[(m0 + m) * Cn + k0 + kk];
            Xs[kk][m] = x[(size_t)(p0 + m) * Cn + k0 + kk];
        }
        __syncthreads();
#pragma unroll
        for (int kk = 0; kk < 16; kk++) {
            unsigned long long wm2[8], xn2[4];
#pragma unroll
            for (int i = 0; i < 8; i++) { float w = Ws[kk][i*16 + tr]; wm2[i] = pack2(w, w); }
#pragma unroll
            for (int j = 0; j < 4; j++)
                xn2[j] = *(const unsigned long long*)&Xs[kk][2 * (j*16 + tc)];
#pragma unroll
            for (int i = 0; i < 8; i++)
#pragma unroll
                for (int j = 0; j < 4; j++) acc[i][j] = ffma2(wm2[i], xn2[j], acc[i][j]);
        }
        __syncthreads();
    }
    int b  = p0 >> 14;
    int l0 = p0 & (Ln - 1);
    size_t base = (size_t)b * OC3 * Ln;
#pragma unroll
    for (int i = 0; i < 8; i++) {
        int m = m0 + i*16 + tr;
        float* row = g_qkv + base + (size_t)m * Ln + l0;
#pragma unroll
        for (int j = 0; j < 4; j++)
            *(unsigned long long*)&row[2 * (j*16 + tc)] = acc[i][j];
    }
}

// ---- K2: softmax over head-dim (32 channels) on q, in place, * d^-0.5 ----
__global__ void k_qsoft() {
    int idx = blockIdx.x * 256 + threadIdx.x;     // over B*H*L
    int l  = idx & (Ln - 1);
    int bh = idx >> 14;                            // 0..31
    int b = bh >> 2, h = bh & 3;
    float* base = g_qkv + (size_t)(b * OC3 + h * Dn) * Ln + l;
    float v[32]; float mx = -1e30f;
#pragma unroll
    for (int d = 0; d < 32; d++) { v[d] = base[(size_t)d * Ln]; mx = fmaxf(mx, v[d]); }
    float s = 0.f;
#pragma unroll
    for (int d = 0; d < 32; d++) { v[d] = __expf(v[d] - mx); s += v[d]; }
    float inv = 0.17677669529663689f / s;          // scale/s
#pragma unroll
    for (int d = 0; d < 32; d++) base[(size_t)d * Ln] = v[d] * inv;
}

// ---- K3: context[bh,c,d] += sum_j exp(k[c,j]) v[d,j]; Z[bh,c] += sum_j exp(k[c,j]) ----
__global__ __launch_bounds__(256) void k_ctx() {
    __shared__ float ks[32][33];
    __shared__ float vs[32][33];
    int t = threadIdx.x;
    int bh = blockIdx.x;     // 0..31
    int b = bh >> 2, h = bh & 3;
    const float* kbase = g_qkv + (size_t)(b * OC3 + Cn     + h * Dn) * Ln;
    const float* vbase = g_qkv + (size_t)(b * OC3 + 2 * Cn + h * Dn) * Ln;
    int j0base = blockIdx.y * 1024;
    int cc = t >> 3;
    int dg = (t & 7) * 4;
    float acc[4] = {0.f, 0.f, 0.f, 0.f};
    float zl = 0.f;

    for (int jb = 0; jb < 32; jb++) {
        int j0 = j0base + jb * 32;
#pragma unroll
        for (int it = 0; it < 4; it++) {
            int idx = it * 256 + t;
            int c = idx >> 5, j = idx & 31;
            ks[c][j] = __expf(kbase[(size_t)c * Ln + j0 + j]);
            vs[c][j] = vbase[(size_t)c * Ln + j0 + j];
        }
        __syncthreads();
#pragma unroll
        for (int j = 0; j < 32; j++) {
            float e = ks[cc][j];
            acc[0] += e * vs[dg    ][j];
            acc[1] += e * vs[dg + 1][j];
            acc[2] += e * vs[dg + 2][j];
            acc[3] += e * vs[dg + 3][j];
        }
        if (t < 32) {
#pragma unroll
            for (int j = 0; j < 32; j++) zl += ks[t][j];
        }
        __syncthreads();
    }
#pragma unroll
    for (int q = 0; q < 4; q++)
        atomicAdd(&g_ctx[bh * 1024 + cc * 32 + dg + q], acc[q]);
    if (t < 32) atomicAdd(&g_Z[bh * 32 + t], zl);
}

// ---- K4: A_b[o, h*32+d] = sum_c Wout[o, h*32+c] * ctx[bh,c,d]/Z[bh,c] ----
__global__ __launch_bounds__(256) void k_A(const float* __restrict__ Wout) {
    __shared__ float cn[Hn * Dn * Dn];   // 4096
    int t = threadIdx.x;
    int b = blockIdx.x;
#pragma unroll
    for (int it = 0; it < 16; it++) {
        int idx = it * 256 + t;
        cn[idx] = g_ctx[b * 4096 + idx] / g_Z[b * 128 + (idx >> 5)];
    }
    __syncthreads();
    for (int it = 0; it < 64; it++) {
        int idx = it * 256 + t;
        int o = idx >> 7, jcol = idx & 127;
        int h = jcol >> 5, d = jcol & 31;
        const float* wrow = Wout + o * Cn + h * Dn;
        const float* cb = cn + h * 1024 + d;
        float s = 0.f;
#pragma unroll
        for (int c = 0; c < 32; c++) s += wrow[c] * cb[c * 32];
        g_A[b * Cn * Cn + idx] = s;
    }
}

// ---- K5: o[b,m,l] = sum_j A_b[m,j] q[b,j,l] + b_out[m]; accumulate sum/sumsq per b ----
__global__ __launch_bounds__(256) void k_out(const float* __restrict__ bout) {
    __shared__ __align__(16) float As[16][132];
    __shared__ __align__(16) float Xs[16][132];
    __shared__ float red[256];
    int t  = threadIdx.x;
    int p0 = blockIdx.x * 128;
    int b  = p0 >> 14;
    int l0 = p0 & (Ln - 1);
    int tr = t >> 4, tc = t & 15;
    const float* Ab = g_A + b * Cn * Cn;
    const float* q  = g_qkv + (size_t)b * OC3 * Ln;   // channels 0..127 = softmaxed q

    unsigned long long acc[8][4];
#pragma unroll
    for (int i = 0; i < 8; i++)
#pragma unroll
        for (int j = 0; j < 4; j++) acc[i][j] = 0ull;

    for (int k0 = 0; k0 < Cn; k0 += 16) {
#pragma unroll
        for (int it = 0; it < 8; it++) {
            int idx = it * 256 + t;
            int m = idx >> 4, kk = idx & 15;
            As[kk][m] = Ab[m * Cn + k0 + kk];
        }
#pragma unroll
        for (int it = 0; it < 8; it++) {
            int idx = it * 256 + t;
            int kk = idx >> 7, n = idx & 127;
            Xs[kk][n] = q[(size_t)(k0 + kk) * Ln + l0 + n];
        }
        __syncthreads();
#pragma unroll
        for (int kk = 0; kk < 16; kk++) {
            unsigned long long wm2[8], xn2[4];
#pragma unroll
            for (int i = 0; i < 8; i++) { float w = As[kk][i*16 + tr]; wm2[i] = pack2(w, w); }
#pragma unroll
            for (int j = 0; j < 4; j++)
                xn2[j] = *(const unsigned long long*)&Xs[kk][2 * (j*16 + tc)];
#pragma unroll
            for (int i = 0; i < 8; i++)
#pragma unroll
                for (int j = 0; j < 4; j++) acc[i][j] = ffma2(wm2[i], xn2[j], acc[i][j]);
        }
        __syncthreads();
    }

    float lsum = 0.f, lsq = 0.f;
#pragma unroll
    for (int i = 0; i < 8; i++) {
        int m = i*16 + tr;
        float bo = bout[m];
        float* row = g_o + (size_t)(b * Cn + m) * Ln + l0;
#pragma unroll
        for (int j = 0; j < 4; j++) {
            float a, bv; unpack2(acc[i][j], a, bv);
            a += bo; bv += bo;
            lsum += a + bv;
            lsq  += a * a + bv * bv;
            *(unsigned long long*)&row[2 * (j*16 + tc)] = pack2(a, bv);
        }
    }
    red[t] = lsum; __syncthreads();
    for (int s = 128; s > 0; s >>= 1) { if (t < s) red[t] += red[t + s]; __syncthreads(); }
    if (t == 0) atomicAdd(&g_bsum[b], red[0]);
    __syncthreads();
    red[t] = lsq; __syncthreads();
    for (int s = 128; s > 0; s >>= 1) { if (t < s) red[t] += red[t + s]; __syncthreads(); }
    if (t == 0) atomicAdd(&g_bsq[b], red[0]);
}

// ---- K6: GroupNorm(1,C) + transpose to [b, l, c] ----
__global__ void k_norm(const float* __restrict__ gnw, const float* __restrict__ gnb,
                       float* __restrict__ out) {
    __shared__ float tile[32][33];
    int b  = blockIdx.z;
    int c0 = blockIdx.y * 32;
    int l0 = blockIdx.x * 32;
    const float n = 2097152.0f;           // C*L
    float mean = g_bsum[b] / n;
    float var  = g_bsq[b] / n - mean * mean;
    float rstd = rsqrtf(var + 1e-5f);
    int tx = threadIdx.x, ty = threadIdx.y;
#pragma unroll
    for (int r = 0; r < 4; r++) {
        int cy = ty * 4 + r;
        tile[cy][tx] = g_o[(size_t)(b * Cn + c0 + cy) * Ln + l0 + tx];
    }
    __syncthreads();
#pragma unroll
    for (int r = 0; r < 4; r++) {
        int ly = ty * 4 + r;
        int cch = c0 + tx;
        float v = (tile[tx][ly] - mean) * rstd * gnw[cch] + gnb[cch];
        out[(size_t)(b * Ln + l0 + ly) * Cn + cch] = v;
    }
}

extern "C" void kernel_launch(void* const* d_in, const int* in_sizes, int n_in,
                              void* d_out, int out_size) {
    const float* x    = (const float*)d_in[0];
    const float* Wqkv = (const float*)d_in[1];
    const float* Wout = (const float*)d_in[2];
    const float* bout = (const float*)d_in[3];
    const float* gnw  = (const float*)d_in[4];
    const float* gnb  = (const float*)d_in[5];
    float* out = (float*)d_out;

    k_zero<<<128, 256>>>();
    k_qkv<<<dim3(BLn / 128, 3), 256>>>(x, Wqkv);
    k_qsoft<<<(Bn * Hn * Ln) / 256, 256>>>();
    k_ctx<<<dim3(Bn * Hn, 16), 256>>>();
    k_A<<<Bn, 256>>>(Wout);
    k_out<<<BLn / 128, 256>>>(bout);
    k_norm<<<dim3(Ln / 32, Cn / 32, Bn), dim3(32, 8)>>>(gnw, gnb, out);
}

// round 9
// speedup vs baseline: 1.5447x; 1.5447x over previous
#include <cuda_runtime.h>
#include <cuda_bf16.h>
#include <cstdint>

#define Bn 8
#define Ln 16384
#define Cn 128
#define Hn 4
#define Dn 32

// ---- scratch (device globals; no allocation allowed) ----
__device__ float g_kv[(size_t)Bn*256*Ln];            // [b, ch, l]: ch 0..127 = exp(k), 128..255 = v
__device__ __nv_bfloat16 g_qbh[(size_t)Bn*Ln*Cn];    // softmaxed q, hi bf16, [b, l, c]
__device__ __nv_bfloat16 g_qbl[(size_t)Bn*Ln*Cn];    // softmaxed q, lo bf16
__device__ float g_o[(size_t)Bn*Cn*Ln];              // pre-norm output [b, c, l]
__device__ float g_ctx[Bn*Hn*Dn*Dn];
__device__ float g_Z[Bn*Hn*Dn];
__device__ __nv_bfloat16 g_Ah[Bn*Cn*Cn];             // folded W_out@blockdiag(ctx), hi
__device__ __nv_bfloat16 g_Al[Bn*Cn*Cn];             // lo
__device__ float g_bsum[Bn];
__device__ float g_bsq[Bn];

// ---- SMEM layout (bytes). Tiles are bf16 with row pitch 136 (68 words). ----
#define PW32 68
#define X_H 0                 // 256 rows * 272B = 69632
#define X_L 69632
#define W_H 139264            // 128 rows * 272B = 34816
#define W_L 174080
#define SM_TOT 208896

// hi/lo bf16 split of a float pair -> packed bf16x2 words
__device__ __forceinline__ void split2(float a, float b, uint32_t& hi, uint32_t& lo) {
    __nv_bfloat162 hp = __floats2bfloat162_rn(a, b);
    hi = *(uint32_t*)&hp;
    __nv_bfloat162 lp = __floats2bfloat162_rn(a - __bfloat162float(hp.x),
                                              b - __bfloat162float(hp.y));
    lo = *(uint32_t*)&lp;
}

__device__ __forceinline__ void mma_bf16(float* c, const uint32_t* a, const uint32_t* b) {
    asm volatile(
        "mma.sync.aligned.m16n8k16.row.col.f32.bf16.bf16.f32 "
        "{%0,%1,%2,%3}, {%4,%5,%6,%7}, {%8,%9}, {%0,%1,%2,%3};"
        : "+f"(c[0]), "+f"(c[1]), "+f"(c[2]), "+f"(c[3])
        : "r"(a[0]), "r"(a[1]), "r"(a[2]), "r"(a[3]), "r"(b[0]), "r"(b[1]));
}

// 3-pass hi/lo GEMM core: acc[mf][nf][4] += A(128xK=128) x B(K=128 x N slice)
// Warp tile 64x64: mf 0..3 (16 rows each), nf 0..7 (8 cols each).
__device__ __forceinline__ void gemm3(const char* smem, float (*acc)[8][4],
                                      int WM, int WN, int g, int t) {
    for (int cb = 0; cb < 3; cb++) {
        const uint32_t* A32 = (const uint32_t*)(smem + (cb == 2 ? W_L : W_H));
        const uint32_t* B32 = (const uint32_t*)(smem + (cb == 1 ? X_L : X_H));
#pragma unroll
        for (int ks = 0; ks < 8; ks++) {
            int ko = ks * 8 + t;
            uint32_t a[4][4], bb[8][2];
#pragma unroll
            for (int mf = 0; mf < 4; mf++) {
                int r = (WM + mf * 16 + g) * PW32 + ko;
                a[mf][0] = A32[r];
                a[mf][1] = A32[r + 8 * PW32];
                a[mf][2] = A32[r + 4];
                a[mf][3] = A32[r + 8 * PW32 + 4];
            }
#pragma unroll
            for (int nf = 0; nf < 8; nf++) {
                int r = (WN + nf * 8 + g) * PW32 + ko;
                bb[nf][0] = B32[r];
                bb[nf][1] = B32[r + 4];
            }
#pragma unroll
            for (int mf = 0; mf < 4; mf++)
#pragma unroll
                for (int nf = 0; nf < 8; nf++)
                    mma_bf16(acc[mf][nf], a[mf], bb[nf]);
        }
    }
}

// ---- K0: zero accumulators (graph replays!) ----
__global__ void k_zero() {
    int i = blockIdx.x * 256 + threadIdx.x;
    if (i < Bn*Hn*Dn*Dn) g_ctx[i] = 0.f;
    if (i < Bn*Hn*Dn)    g_Z[i]   = 0.f;
    if (i < Bn)          { g_bsum[i] = 0.f; g_bsq[i] = 0.f; }
}

// ======== K1: HMMA QKV GEMM + fused q-softmax + exp(k) ========
// CTA: 256 positions x 3 m-tiles of 128 out channels, K=128.
__global__ __launch_bounds__(256, 1) void k_qkv_mma(const float* __restrict__ x,
                                                    const float* __restrict__ Wqkv) {
    extern __shared__ __align__(16) char smem[];
    int tid = threadIdx.x, wid = tid >> 5, lid = tid & 31;
    int g = lid >> 2, t = lid & 3;
    int WM = (wid & 1) * 64, WN = (wid >> 1) * 64;
    int p0 = blockIdx.x * 256;
    int b = p0 >> 14, l0 = p0 & (Ln - 1);
    uint32_t* XH = (uint32_t*)(smem + X_H);
    uint32_t* XL = (uint32_t*)(smem + X_L);
    uint32_t* WHp = (uint32_t*)(smem + W_H);
    uint32_t* WLp = (uint32_t*)(smem + W_L);

    // ---- load + split X tile: 256 pos x 128 ch ----
    const float4* x4 = (const float4*)(x + (size_t)p0 * Cn);
#pragma unroll
    for (int it = 0; it < 32; it++) {
        int f = it * 256 + tid, row = f >> 5, u = f & 31;
        float4 v = x4[f];
        uint32_t h0, l0w, h1, l1w;
        split2(v.x, v.y, h0, l0w);
        split2(v.z, v.w, h1, l1w);
        int wb = row * PW32 + u * 2;
        XH[wb] = h0; XH[wb + 1] = h1;
        XL[wb] = l0w; XL[wb + 1] = l1w;
    }

    for (int mt = 0; mt < 3; mt++) {
        // ---- load + split W m-tile: 128 x 128 ----
        const float4* w4 = (const float4*)(Wqkv + (size_t)mt * Cn * Cn);
#pragma unroll
        for (int it = 0; it < 16; it++) {
            int f = it * 256 + tid, row = f >> 5, u = f & 31;
            float4 v = w4[f];
            uint32_t h0, l0w, h1, l1w;
            split2(v.x, v.y, h0, l0w);
            split2(v.z, v.w, h1, l1w);
            int wb = row * PW32 + u * 2;
            WHp[wb] = h0; WHp[wb + 1] = h1;
            WLp[wb] = l0w; WLp[wb + 1] = l1w;
        }
        __syncthreads();

        float acc[4][8][4];
#pragma unroll
        for (int mf = 0; mf < 4; mf++)
#pragma unroll
            for (int nf = 0; nf < 8; nf++)
#pragma unroll
                for (int q = 0; q < 4; q++) acc[mf][nf][q] = 0.f;

        gemm3(smem, acc, WM, WN, g, t);
        __syncthreads();

        if (mt == 0) {
            // q: stage transposed in W region (2 rounds of 128 positions), softmax
            float* qs = (float*)(smem + W_H);
            for (int r = 0; r < 2; r++) {
                if ((WN >> 7) == r) {
#pragma unroll
                    for (int mf = 0; mf < 4; mf++)
#pragma unroll
                        for (int nf = 0; nf < 8; nf++) {
                            int m = WM + mf * 16 + g;
                            int nl = WN + nf * 8 + 2 * t - r * 128;
                            qs[nl * 129 + m]           = acc[mf][nf][0];
                            qs[(nl + 1) * 129 + m]     = acc[mf][nf][1];
                            qs[nl * 129 + m + 8]       = acc[mf][nf][2];
                            qs[(nl + 1) * 129 + m + 8] = acc[mf][nf][3];
                        }
                }
                __syncthreads();
                int pos = tid >> 1, hb = (tid & 1) * 64;
                size_t gq = ((size_t)(b * Ln + l0 + r * 128 + pos)) * Cn + hb;
#pragma unroll
                for (int hh = 0; hh < 2; hh++) {
                    float vv[32]; float mx = -1e30f;
#pragma unroll
                    for (int d = 0; d < 32; d++) {
                        vv[d] = qs[pos * 129 + hb + hh * 32 + d];
                        mx = fmaxf(mx, vv[d]);
                    }
                    float s = 0.f;
#pragma unroll
                    for (int d = 0; d < 32; d++) { vv[d] = __expf(vv[d] - mx); s += vv[d]; }
                    float inv = 0.17677669529663689f / s;   // d^-0.5 / s
                    uint32_t ph[16], pl[16];
#pragma unroll
                    for (int d2 = 0; d2 < 16; d2++)
                        split2(vv[2 * d2] * inv, vv[2 * d2 + 1] * inv, ph[d2], pl[d2]);
                    uint4* dh = (uint4*)(g_qbh + gq + hh * 32);
                    uint4* dl = (uint4*)(g_qbl + gq + hh * 32);
#pragma unroll
                    for (int w = 0; w < 4; w++) {
                        dh[w] = make_uint4(ph[4*w], ph[4*w+1], ph[4*w+2], ph[4*w+3]);
                        dl[w] = make_uint4(pl[4*w], pl[4*w+1], pl[4*w+2], pl[4*w+3]);
                    }
                }
                __syncthreads();
            }
        } else {
            // k -> exp(k); v -> raw; channel-major [b, ch, l]
            float* gk = g_kv + ((size_t)(b * 256 + (mt - 1) * 128)) * Ln + l0;
#pragma unroll
            for (int mf = 0; mf < 4; mf++)
#pragma unroll
                for (int nf = 0; nf < 8; nf++) {
                    int m = WM + mf * 16 + g;
                    int n0 = WN + nf * 8 + 2 * t;
                    float c0 = acc[mf][nf][0], c1 = acc[mf][nf][1];
                    float c2 = acc[mf][nf][2], c3 = acc[mf][nf][3];
                    if (mt == 1) {
                        c0 = __expf(c0); c1 = __expf(c1);
                        c2 = __expf(c2); c3 = __expf(c3);
                    }
                    *(float2*)(gk + (size_t)m * Ln + n0)       = make_float2(c0, c1);
                    *(float2*)(gk + (size_t)(m + 8) * Ln + n0) = make_float2(c2, c3);
                }
            __syncthreads();
        }
    }
}

// ---- K3: context[bh,c,d] += sum_j ek[c,j] v[d,j]; Z[bh,c] += sum_j ek[c,j] ----
__global__ __launch_bounds__(256) void k_ctx() {
    __shared__ float ks[32][33];
    __shared__ float vs[32][33];
    int t = threadIdx.x;
    int bh = blockIdx.x;
    int b = bh >> 2, h = bh & 3;
    const float* kbase = g_kv + (size_t)(b * 256 + h * Dn) * Ln;
    const float* vbase = g_kv + (size_t)(b * 256 + 128 + h * Dn) * Ln;
    int j0base = blockIdx.y * 1024;
    int g = t >> 6;
    int w = t & 63;
    int c4 = (w >> 3) * 4;
    int d4 = (w & 7) * 4;
    float acc[4][4];
#pragma unroll
    for (int i = 0; i < 4; i++)
#pragma unroll
        for (int k = 0; k < 4; k++) acc[i][k] = 0.f;
    float zl = 0.f;

    for (int jb = 0; jb < 32; jb++) {
        int j0 = j0base + jb * 32;
#pragma unroll
        for (int it = 0; it < 4; it++) {
            int idx = it * 256 + t;
            int c = idx >> 5, j = idx & 31;
            ks[c][j] = kbase[(size_t)c * Ln + j0 + j];
            vs[c][j] = vbase[(size_t)c * Ln + j0 + j];
        }
        __syncthreads();
#pragma unroll
        for (int jj = 0; jj < 8; jj++) {
            int j = g * 8 + jj;
            float e[4], v[4];
#pragma unroll
            for (int i = 0; i < 4; i++) { e[i] = ks[c4 + i][j]; v[i] = vs[d4 + i][j]; }
#pragma unroll
            for (int i = 0; i < 4; i++)
#pragma unroll
                for (int k = 0; k < 4; k++) acc[i][k] += e[i] * v[k];
        }
        if (w < 32) {
#pragma unroll
            for (int jj = 0; jj < 8; jj++) zl += ks[w][g * 8 + jj];
        }
        __syncthreads();
    }
#pragma unroll
    for (int i = 0; i < 4; i++)
#pragma unroll
        for (int k = 0; k < 4; k++)
            atomicAdd(&g_ctx[bh * 1024 + (c4 + i) * 32 + d4 + k], acc[i][k]);
    if (w < 32) atomicAdd(&g_Z[bh * 32 + w], zl);
}

// ---- K4: A_b = Wout @ blockdiag(ctx/Z), output bf16 hi/lo ----
__global__ __launch_bounds__(256) void k_A(const float* __restrict__ Wout) {
    __shared__ float cn[Hn * Dn * Dn];
    int t = threadIdx.x;
    int b = blockIdx.x;
#pragma unroll
    for (int it = 0; it < 16; it++) {
        int idx = it * 256 + t;
        cn[idx] = g_ctx[b * 4096 + idx] / g_Z[b * 128 + (idx >> 5)];
    }
    __syncthreads();
    for (int it = 0; it < 64; it++) {
        int idx = it * 256 + t;
        int o = idx >> 7, jcol = idx & 127;
        int h = jcol >> 5, d = jcol & 31;
        const float* wrow = Wout + o * Cn + h * Dn;
        const float* cb = cn + h * 1024 + d;
        float s = 0.f;
#pragma unroll
        for (int c = 0; c < 32; c++) s += wrow[c] * cb[c * 32];
        __nv_bfloat16 hb = __float2bfloat16(s);
        g_Ah[b * Cn * Cn + idx] = hb;
        g_Al[b * Cn * Cn + idx] = __float2bfloat16(s - __bfloat162float(hb));
    }
}

// ======== K5: HMMA out GEMM: o = A_b @ q + bias; accumulate sum/sumsq ========
__global__ __launch_bounds__(256, 1) void k_out_mma(const float* __restrict__ bout) {
    extern __shared__ __align__(16) char smem[];
    int tid = threadIdx.x, wid = tid >> 5, lid = tid & 31;
    int g = lid >> 2, t = lid & 3;
    int WM = (wid & 1) * 64, WN = (wid >> 1) * 64;
    int p0 = blockIdx.x * 256;
    int b = p0 >> 14, l0 = p0 & (Ln - 1);
    uint32_t* XH = (uint32_t*)(smem + X_H);
    uint32_t* XL = (uint32_t*)(smem + X_L);
    uint32_t* WHp = (uint32_t*)(smem + W_H);
    uint32_t* WLp = (uint32_t*)(smem + W_L);

    // Q tiles (already bf16 hi/lo, [l][c] K-major rows of 256B)
    const uint4* qh4 = (const uint4*)(g_qbh + (size_t)p0 * Cn);
    const uint4* ql4 = (const uint4*)(g_qbl + (size_t)p0 * Cn);
#pragma unroll
    for (int it = 0; it < 16; it++) {
        int f = it * 256 + tid, row = f >> 4, u = f & 15;
        *(uint4*)(XH + row * PW32 + u * 4) = qh4[f];
        *(uint4*)(XL + row * PW32 + u * 4) = ql4[f];
    }
    // A tiles
    const uint4* ah4 = (const uint4*)(g_Ah + (size_t)b * Cn * Cn);
    const uint4* al4 = (const uint4*)(g_Al + (size_t)b * Cn * Cn);
#pragma unroll
    for (int it = 0; it < 8; it++) {
        int f = it * 256 + tid, row = f >> 4, u = f & 15;
        *(uint4*)(WHp + row * PW32 + u * 4) = ah4[f];
        *(uint4*)(WLp + row * PW32 + u * 4) = al4[f];
    }
    __syncthreads();

    float acc[4][8][4];
#pragma unroll
    for (int mf = 0; mf < 4; mf++)
#pragma unroll
        for (int nf = 0; nf < 8; nf++)
#pragma unroll
            for (int q = 0; q < 4; q++) acc[mf][nf][q] = 0.f;

    gemm3(smem, acc, WM, WN, g, t);
    __syncthreads();

    float lsum = 0.f, lsq = 0.f;
    float* go = g_o + ((size_t)b * Cn) * Ln + l0;
#pragma unroll
    for (int mf = 0; mf < 4; mf++) {
        int m = WM + mf * 16 + g;
        float b0v = bout[m], b1v = bout[m + 8];
#pragma unroll
        for (int nf = 0; nf < 8; nf++) {
            int n0 = WN + nf * 8 + 2 * t;
            float c0 = acc[mf][nf][0] + b0v, c1 = acc[mf][nf][1] + b0v;
            float c2 = acc[mf][nf][2] + b1v, c3 = acc[mf][nf][3] + b1v;
            lsum += c0 + c1 + c2 + c3;
            lsq  += c0 * c0 + c1 * c1 + c2 * c2 + c3 * c3;
            *(float2*)(go + (size_t)m * Ln + n0)       = make_float2(c0, c1);
            *(float2*)(go + (size_t)(m + 8) * Ln + n0) = make_float2(c2, c3);
        }
    }
    float* red = (float*)(smem + W_H);
    red[tid] = lsum; __syncthreads();
    for (int s = 128; s > 0; s >>= 1) { if (tid < s) red[tid] += red[tid + s]; __syncthreads(); }
    if (tid == 0) atomicAdd(&g_bsum[b], red[0]);
    __syncthreads();
    red[tid] = lsq; __syncthreads();
    for (int s = 128; s > 0; s >>= 1) { if (tid < s) red[tid] += red[tid + s]; __syncthreads(); }
    if (tid == 0) atomicAdd(&g_bsq[b], red[0]);
}

// ---- K6: GroupNorm(1,C) + transpose to [b, l, c] ----
__global__ void k_norm(const float* __restrict__ gnw, const float* __restrict__ gnb,
                       float* __restrict__ out) {
    __shared__ float tile[32][33];
    int b  = blockIdx.z;
    int c0 = blockIdx.y * 32;
    int l0 = blockIdx.x * 32;
    const float n = 2097152.0f;           // C*L
    float mean = g_bsum[b] / n;
    float var  = g_bsq[b] / n - mean * mean;
    float rstd = rsqrtf(var + 1e-5f);
    int tx = threadIdx.x, ty = threadIdx.y;
#pragma unroll
    for (int r = 0; r < 4; r++) {
        int cy = ty * 4 + r;
        tile[cy][tx] = g_o[(size_t)(b * Cn + c0 + cy) * Ln + l0 + tx];
    }
    __syncthreads();
#pragma unroll
    for (int r = 0; r < 4; r++) {
        int ly = ty * 4 + r;
        int cch = c0 + tx;
        float v = (tile[tx][ly] - mean) * rstd * gnw[cch] + gnb[cch];
        out[(size_t)(b * Ln + l0 + ly) * Cn + cch] = v;
    }
}

extern "C" void kernel_launch(void* const* d_in, const int* in_sizes, int n_in,
                              void* d_out, int out_size) {
    const float* x    = (const float*)d_in[0];
    const float* Wqkv = (const float*)d_in[1];
    const float* Wout = (const float*)d_in[2];
    const float* bout = (const float*)d_in[3];
    const float* gnw  = (const float*)d_in[4];
    const float* gnb  = (const float*)d_in[5];
    float* out = (float*)d_out;

    cudaFuncSetAttribute(k_qkv_mma, cudaFuncAttributeMaxDynamicSharedMemorySize, SM_TOT);
    cudaFuncSetAttribute(k_out_mma, cudaFuncAttributeMaxDynamicSharedMemorySize, SM_TOT);

    k_zero<<<128, 256>>>();
    k_qkv_mma<<<(Bn * Ln) / 256, 256, SM_TOT>>>(x, Wqkv);
    k_ctx<<<dim3(Bn * Hn, 16), 256>>>();
    k_A<<<Bn, 256>>>(Wout);
    k_out_mma<<<(Bn * Ln) / 256, 256, SM_TOT>>>(bout);
    k_norm<<<dim3(Ln / 32, Cn / 32, Bn), dim3(32, 8)>>>(gnw, gnb, out);
}